// round 9
// baseline (speedup 1.0000x reference)
#include <cuda_runtime.h>

// BackEdgeConv2d fused: out = x * !(5 <= boxcount7x7(x >= 128/255, reflect) <= 19)
// x: [16,3,1024,1024] fp32. R8 phase 1 (fast path + sign pack), rolling uint4
// phase 2 (full thread utilization), R3 dp4a phase 3. Rows padded to 144B.

#define TILE_W 128
#define TILE_H 64
#define KPAD 3
#define PH (TILE_H + 2*KPAD)        // 70 padded rows
#define WPR 36                      // words per row (144 B, 16B-aligned); 34 valid
#define U4PR 9                      // uint4 per row
#define NTHREADS 256

// PTX prmt: guaranteed default-mode semantics (byte gather).
__device__ __forceinline__ unsigned prmt(unsigned a, unsigned b, unsigned s) {
    unsigned r;
    asm("prmt.b32 %0, %1, %2, %3;" : "=r"(r) : "r"(a), "r"(b), "r"(s));
    return r;
}

__global__ __launch_bounds__(NTHREADS)
void backedge_kernel(const float* __restrict__ x, float* __restrict__ out,
                     int H, int W) {
    __shared__ __align__(16) unsigned int scond[PH * WPR];      // 10080 B
    __shared__ __align__(16) unsigned int svsum[TILE_H * WPR];  // 9216 B

    const int tid = threadIdx.x;
    const int c0 = blockIdx.x * TILE_W;
    const int r0 = blockIdx.y * TILE_H;
    const long long plane = (long long)blockIdx.z * H * W;
    const float* xp = x + plane;
    float* op = out + plane;
    const float T = 128.0f / 255.0f;

    // ---- Phase 1: padded binary cond map; byte j <-> global col (c0 - 4 + j),
    //      valid j < 136; words 34,35 per row are zero pad.
    //      cond = (x >= T) = !signbit(x - T)  (x==T -> +0 -> 1; exact).
    const bool interior = (c0 >= 4) && (c0 + TILE_W + 4 <= W) &&
                          (r0 >= KPAD) && (r0 + TILE_H + KPAD <= H);
    if (interior) {
        const float* base = xp + (r0 - KPAD) * W + (c0 - 4);
        #pragma unroll 1
        for (int wi = tid; wi < PH * WPR; wi += NTHREADS) {
            int pr = wi / WPR;                // const divisor -> mul.hi
            int w  = wi - pr * WPR;
            unsigned cw = 0u;
            if (w < 34) {
                const float4 v = *(const float4*)(base + pr * W + (w << 2));
                unsigned a0 = __float_as_uint(v.x - T);
                unsigned a1 = __float_as_uint(v.y - T);
                unsigned a2 = __float_as_uint(v.z - T);
                unsigned a3 = __float_as_uint(v.w - T);
                unsigned sa = prmt(prmt(a0, a1, 0x0073), prmt(a2, a3, 0x0073), 0x5410);
                cw = ((~sa) & 0x80808080u) >> 7;        // 1/0 per byte
            }
            scond[wi] = cw;
        }
    } else {
        #pragma unroll 1
        for (int wi = tid; wi < PH * WPR; wi += NTHREADS) {
            int pr = wi / WPR;
            int w  = wi - pr * WPR;
            unsigned cw = 0u;
            if (w < 34) {
                int gr = r0 + pr - KPAD;
                int gc = c0 + (w << 2) - 4;
                float4 v;
                if ((unsigned)gr < (unsigned)H && (unsigned)gc <= (unsigned)(W - 4)) {
                    v = *(const float4*)(xp + gr * W + gc);
                } else {
                    int rr = gr < 0 ? -gr : (gr >= H ? 2 * H - 2 - gr : gr);
                    const float* rowp = xp + rr * W;
                    int g0 = gc, g1 = gc + 1, g2 = gc + 2, g3 = gc + 3;
                    g0 = g0 < 0 ? -g0 : (g0 >= W ? 2 * W - 2 - g0 : g0);
                    g1 = g1 < 0 ? -g1 : (g1 >= W ? 2 * W - 2 - g1 : g1);
                    g2 = g2 < 0 ? -g2 : (g2 >= W ? 2 * W - 2 - g2 : g2);
                    g3 = g3 < 0 ? -g3 : (g3 >= W ? 2 * W - 2 - g3 : g3);
                    v.x = rowp[g0]; v.y = rowp[g1]; v.z = rowp[g2]; v.w = rowp[g3];
                }
                unsigned a0 = __float_as_uint(v.x - T);
                unsigned a1 = __float_as_uint(v.y - T);
                unsigned a2 = __float_as_uint(v.z - T);
                unsigned a3 = __float_as_uint(v.w - T);
                unsigned sa = prmt(prmt(a0, a1, 0x0073), prmt(a2, a3, 0x0073), 0x5410);
                cw = ((~sa) & 0x80808080u) >> 7;
            }
            scond[wi] = cw;
        }
    }
    __syncthreads();

    // ---- Phase 2: vertical 7-sum, rolling 2-row bands, uint4 byte-SIMD.
    //      Tasks = 32 bands x 9 uint4-cols = 288; all 256 threads active.
    {
        const uint4* c4 = (const uint4*)scond;
        uint4* v4 = (uint4*)svsum;
        #pragma unroll 1
        for (int t = tid; t < (TILE_H / 2) * U4PR; t += NTHREADS) {
            int band = t / U4PR;              // const divisor
            int col  = t - band * U4PR;
            int rb = band << 1;
            const uint4* base = c4 + col;
            uint4 s = base[rb * U4PR];
            #pragma unroll
            for (int k = 1; k < 7; k++) {
                uint4 a = base[(rb + k) * U4PR];
                s.x += a.x; s.y += a.y; s.z += a.z; s.w += a.w;
            }
            v4[rb * U4PR + col] = s;
            uint4 ad = base[(rb + 7) * U4PR];
            uint4 su = base[rb * U4PR];
            s.x += ad.x - su.x;  s.y += ad.y - su.y;   // byte-exact (mod 2^32)
            s.z += ad.z - su.z;  s.w += ad.w - su.w;
            v4[(rb + 1) * U4PR + col] = s;
        }
    }
    __syncthreads();

    // ---- Phase 3: horizontal sliding 7-sum via dp4a, 4 px/thread/row
    const int tx = tid & 31;        // word group -> cols [4tx .. 4tx+3]
    const int ty = tid >> 5;
    const unsigned int* vrow = &svsum[ty * WPR + tx];
    const float* gp = xp + (long long)(r0 + ty) * W + c0 + (tx << 2);
    float* gop = op + (long long)(r0 + ty) * W + c0 + (tx << 2);

    #pragma unroll
    for (int rr = 0; rr < TILE_H; rr += 8) {
        unsigned int w0 = vrow[0];
        unsigned int w1 = vrow[1];
        unsigned int w2 = vrow[2];

        // window bytes a1..a10 of the 12-byte span starting at byte 4*tx
        int h0 = __dp4a(w0, 0x01010100u, 0u);           // a1+a2+a3
        h0 = __dp4a(w1, 0x01010101u, (unsigned)h0);     // + a4..a7
        int a1  = (w0 >> 8)  & 0xFF;
        int a2  = (w0 >> 16) & 0xFF;
        int a3  = (w0 >> 24) & 0xFF;
        int a8  =  w2        & 0xFF;
        int a9  = (w2 >> 8)  & 0xFF;
        int a10 = (w2 >> 16) & 0xFF;
        int h1 = h0 - a1 + a8;
        int h2 = h1 - a2 + a9;
        int h3 = h2 - a3 + a10;

        float4 xv = *(const float4*)gp;
        float4 ov;
        ov.x = ((unsigned)(h0 - 5) <= 14u) ? 0.0f : xv.x;   // band 5..19 inclusive
        ov.y = ((unsigned)(h1 - 5) <= 14u) ? 0.0f : xv.y;
        ov.z = ((unsigned)(h2 - 5) <= 14u) ? 0.0f : xv.z;
        ov.w = ((unsigned)(h3 - 5) <= 14u) ? 0.0f : xv.w;

        __stcs((float4*)gop, ov);

        vrow += 8 * WPR;
        gp  += 8 * W;
        gop += 8 * W;
    }
}

extern "C" void kernel_launch(void* const* d_in, const int* in_sizes, int n_in,
                              void* d_out, int out_size) {
    const float* x = (const float*)d_in[0];
    float* out = (float*)d_out;
    const int H = 1024, W = 1024;
    const int planes = out_size / (H * W);   // B*C = 48
    dim3 grid(W / TILE_W, H / TILE_H, planes);
    backedge_kernel<<<grid, NTHREADS>>>(x, out, H, W);
}

// round 10
// speedup vs baseline: 1.1130x; 1.1130x over previous
#include <cuda_runtime.h>

// BackEdgeConv2d fused: out = x * !(5 <= boxcount7x7(x >= 128/255, reflect) <= 19)
// x: [16,3,1024,1024] fp32. R8 skeleton; phase 2 = 2-row rolling uint2 bands.

#define TILE_W 128
#define TILE_H 64
#define KPAD 3
#define PH (TILE_H + 2*KPAD)        // 70 padded rows
#define WPR 34                      // 136 cond bytes/row: byte j <-> global col c0-4+j
#define W2PR 17                     // uint2 per row
#define NTHREADS 256

// PTX prmt: guaranteed default-mode semantics (byte gather).
__device__ __forceinline__ unsigned prmt(unsigned a, unsigned b, unsigned s) {
    unsigned r;
    asm("prmt.b32 %0, %1, %2, %3;" : "=r"(r) : "r"(a), "r"(b), "r"(s));
    return r;
}

__global__ __launch_bounds__(NTHREADS)
void backedge_kernel(const float* __restrict__ x, float* __restrict__ out,
                     int H, int W) {
    __shared__ __align__(16) unsigned int scond[PH * WPR];      // 9520 B
    __shared__ __align__(16) unsigned int svsum[TILE_H * WPR];  // 8704 B

    const int tid = threadIdx.x;
    const int c0 = blockIdx.x * TILE_W;
    const int r0 = blockIdx.y * TILE_H;
    const long long plane = (long long)blockIdx.z * H * W;
    const float* xp = x + plane;
    float* op = out + plane;
    const float T = 128.0f / 255.0f;

    // ---- Phase 1: padded binary cond map, one uint32 word (4 px) per iter.
    //      cond = (x >= T) = !signbit(x - T)  (x==T -> +0 -> 1; exact).
    const bool interior = (c0 >= 4) && (c0 + TILE_W + 4 <= W) &&
                          (r0 >= KPAD) && (r0 + TILE_H + KPAD <= H);
    if (interior) {
        const float* base = xp + (r0 - KPAD) * W + (c0 - 4);
        #pragma unroll 1
        for (int wi = tid; wi < PH * WPR; wi += NTHREADS) {
            int pr = wi / WPR;                // const divisor -> mul.hi
            int w  = wi - pr * WPR;
            const float4 v = *(const float4*)(base + pr * W + (w << 2));
            unsigned a0 = __float_as_uint(v.x - T);
            unsigned a1 = __float_as_uint(v.y - T);
            unsigned a2 = __float_as_uint(v.z - T);
            unsigned a3 = __float_as_uint(v.w - T);
            unsigned sa = prmt(prmt(a0, a1, 0x0073), prmt(a2, a3, 0x0073), 0x5410);
            scond[wi] = ((~sa) & 0x80808080u) >> 7;     // 1/0 per byte
        }
    } else {
        #pragma unroll 1
        for (int wi = tid; wi < PH * WPR; wi += NTHREADS) {
            int pr = wi / WPR;
            int w  = wi - pr * WPR;
            int gr = r0 + pr - KPAD;
            int gc = c0 + (w << 2) - 4;
            float4 v;
            if ((unsigned)gr < (unsigned)H && (unsigned)gc <= (unsigned)(W - 4)) {
                v = *(const float4*)(xp + gr * W + gc);
            } else {
                int rr = gr < 0 ? -gr : (gr >= H ? 2 * H - 2 - gr : gr);
                const float* rowp = xp + rr * W;
                int g0 = gc, g1 = gc + 1, g2 = gc + 2, g3 = gc + 3;
                g0 = g0 < 0 ? -g0 : (g0 >= W ? 2 * W - 2 - g0 : g0);
                g1 = g1 < 0 ? -g1 : (g1 >= W ? 2 * W - 2 - g1 : g1);
                g2 = g2 < 0 ? -g2 : (g2 >= W ? 2 * W - 2 - g2 : g2);
                g3 = g3 < 0 ? -g3 : (g3 >= W ? 2 * W - 2 - g3 : g3);
                v.x = rowp[g0]; v.y = rowp[g1]; v.z = rowp[g2]; v.w = rowp[g3];
            }
            unsigned a0 = __float_as_uint(v.x - T);
            unsigned a1 = __float_as_uint(v.y - T);
            unsigned a2 = __float_as_uint(v.z - T);
            unsigned a3 = __float_as_uint(v.w - T);
            unsigned sa = prmt(prmt(a0, a1, 0x0073), prmt(a2, a3, 0x0073), 0x5410);
            scond[wi] = ((~sa) & 0x80808080u) >> 7;
        }
    }
    __syncthreads();

    // ---- Phase 2: vertical 7-sum, 2-row rolling bands, uint2 byte-SIMD.
    //      Tasks = 32 bands x 17 uint2-cols = 544; 8 LDS.64 + 2 STS.64 per task.
    {
        const uint2* c2 = (const uint2*)scond;
        uint2* v2 = (uint2*)svsum;
        #pragma unroll 1
        for (int t = tid; t < (TILE_H / 2) * W2PR; t += NTHREADS) {
            int band = t / W2PR;              // const divisor
            int col  = t - band * W2PR;
            int rb = band << 1;
            const uint2* base = c2 + col;
            uint2 first = base[rb * W2PR];
            uint2 s = first;
            #pragma unroll
            for (int k = 1; k < 7; k++) {
                uint2 a = base[(rb + k) * W2PR];
                s.x += a.x; s.y += a.y;
            }
            v2[rb * W2PR + col] = s;
            uint2 ad = base[(rb + 7) * W2PR];
            s.x += ad.x - first.x;            // byte-exact (counts <= 7, mod 2^32)
            s.y += ad.y - first.y;
            v2[(rb + 1) * W2PR + col] = s;
        }
    }
    __syncthreads();

    // ---- Phase 3: horizontal sliding 7-sum via dp4a, 4 px/thread/row (== R8)
    const int tx = tid & 31;        // word group -> cols [4tx .. 4tx+3]
    const int ty = tid >> 5;
    const unsigned int* vrow = &svsum[ty * WPR + tx];
    const float* gp = xp + (long long)(r0 + ty) * W + c0 + (tx << 2);
    float* gop = op + (long long)(r0 + ty) * W + c0 + (tx << 2);

    #pragma unroll
    for (int rr = 0; rr < TILE_H; rr += 8) {
        unsigned int w0 = vrow[0];
        unsigned int w1 = vrow[1];
        unsigned int w2 = vrow[2];

        // window bytes a1..a10 of the 12-byte span starting at byte 4*tx
        int h0 = __dp4a(w0, 0x01010100u, 0u);           // a1+a2+a3
        h0 = __dp4a(w1, 0x01010101u, (unsigned)h0);     // + a4..a7
        int a1  = (w0 >> 8)  & 0xFF;
        int a2  = (w0 >> 16) & 0xFF;
        int a3  = (w0 >> 24) & 0xFF;
        int a8  =  w2        & 0xFF;
        int a9  = (w2 >> 8)  & 0xFF;
        int a10 = (w2 >> 16) & 0xFF;
        int h1 = h0 - a1 + a8;
        int h2 = h1 - a2 + a9;
        int h3 = h2 - a3 + a10;

        float4 xv = *(const float4*)gp;
        float4 ov;
        ov.x = ((unsigned)(h0 - 5) <= 14u) ? 0.0f : xv.x;   // band 5..19 inclusive
        ov.y = ((unsigned)(h1 - 5) <= 14u) ? 0.0f : xv.y;
        ov.z = ((unsigned)(h2 - 5) <= 14u) ? 0.0f : xv.z;
        ov.w = ((unsigned)(h3 - 5) <= 14u) ? 0.0f : xv.w;

        __stcs((float4*)gop, ov);

        vrow += 8 * WPR;
        gp  += 8 * W;
        gop += 8 * W;
    }
}

extern "C" void kernel_launch(void* const* d_in, const int* in_sizes, int n_in,
                              void* d_out, int out_size) {
    const float* x = (const float*)d_in[0];
    float* out = (float*)d_out;
    const int H = 1024, W = 1024;
    const int planes = out_size / (H * W);   // B*C = 48
    dim3 grid(W / TILE_W, H / TILE_H, planes);
    backedge_kernel<<<grid, NTHREADS>>>(x, out, H, W);
}

// round 11
// speedup vs baseline: 1.2363x; 1.1108x over previous
#include <cuda_runtime.h>

// BackEdgeConv2d fused: out = x * !(5 <= boxcount7x7(x >= 128/255, reflect) <= 19)
// x: [16,3,1024,1024] fp32. R8 skeleton (memory shapes frozen):
//  - phase 1: interior fast path, sign-bit pack, word-PAIR tasks (17 uint2/row)
//  - phase 2: R8 verbatim (7-load vertical sums, uint2 grid-stride)
//  - phase 3: same loads/stores; SIMD prefix-sum + byte band mask (R5 math)

#define TILE_W 128
#define TILE_H 64
#define KPAD 3
#define PH (TILE_H + 2*KPAD)        // 70 padded rows
#define WPR 34                      // 136 cond bytes/row: byte j <-> global col c0-4+j
#define PPR 17                      // uint2 pairs per row (exactly 34 words)
#define W2PR 17                     // uint2 per row (phase 2 view)
#define NTHREADS 256

// PTX prmt: guaranteed default-mode semantics incl. selector-bit-3 MSB-replicate.
__device__ __forceinline__ unsigned prmt(unsigned a, unsigned b, unsigned s) {
    unsigned r;
    asm("prmt.b32 %0, %1, %2, %3;" : "=r"(r) : "r"(a), "r"(b), "r"(s));
    return r;
}

__device__ __forceinline__ unsigned pack4(float4 v, float T) {
    // cond = (x >= T) = !signbit(x - T); x==T -> +0 -> 1. Exact.
    unsigned a0 = __float_as_uint(v.x - T);
    unsigned a1 = __float_as_uint(v.y - T);
    unsigned a2 = __float_as_uint(v.z - T);
    unsigned a3 = __float_as_uint(v.w - T);
    unsigned sa = prmt(prmt(a0, a1, 0x0073), prmt(a2, a3, 0x0073), 0x5410);
    return ((~sa) & 0x80808080u) >> 7;          // 1/0 per byte
}

__global__ __launch_bounds__(NTHREADS)
void backedge_kernel(const float* __restrict__ x, float* __restrict__ out,
                     int H, int W) {
    __shared__ __align__(16) unsigned int scond[PH * WPR];      // 9520 B
    __shared__ __align__(16) unsigned int svsum[TILE_H * WPR];  // 8704 B

    const int tid = threadIdx.x;
    const int c0 = blockIdx.x * TILE_W;
    const int r0 = blockIdx.y * TILE_H;
    const long long plane = (long long)blockIdx.z * H * W;
    const float* xp = x + plane;
    float* op = out + plane;
    const float T = 128.0f / 255.0f;

    // ---- Phase 1: padded binary cond map; one word-PAIR (8 px) per task.
    const bool interior = (c0 >= 4) && (c0 + TILE_W + 4 <= W) &&
                          (r0 >= KPAD) && (r0 + TILE_H + KPAD <= H);
    if (interior) {
        const float* base = xp + (r0 - KPAD) * W + (c0 - 4);
        #pragma unroll 1
        for (int t = tid; t < PH * PPR; t += NTHREADS) {
            int pr = t / PPR;                 // const divisor -> mul.hi
            int pw = t - pr * PPR;
            const float4* p = (const float4*)(base + pr * W + (pw << 3));
            float4 va = p[0], vb = p[1];
            uint2 cw;
            cw.x = pack4(va, T);
            cw.y = pack4(vb, T);
            ((uint2*)scond)[t] = cw;
        }
    } else {
        #pragma unroll 1
        for (int t = tid; t < PH * PPR; t += NTHREADS) {
            int pr = t / PPR;
            int pw = t - pr * PPR;
            int gr = r0 + pr - KPAD;
            int gc = c0 + (pw << 3) - 4;
            float4 va, vb;
            if ((unsigned)gr < (unsigned)H && (unsigned)gc <= (unsigned)(W - 8)) {
                const float4* p = (const float4*)(xp + gr * W + gc);
                va = p[0]; vb = p[1];
            } else {
                int rr = gr < 0 ? -gr : (gr >= H ? 2 * H - 2 - gr : gr);
                const float* rowp = xp + rr * W;
                float f[8];
                #pragma unroll
                for (int k = 0; k < 8; k++) {
                    int g = gc + k;
                    g = g < 0 ? -g : (g >= W ? 2 * W - 2 - g : g);
                    f[k] = rowp[g];
                }
                va = make_float4(f[0], f[1], f[2], f[3]);
                vb = make_float4(f[4], f[5], f[6], f[7]);
            }
            uint2 cw;
            cw.x = pack4(va, T);
            cw.y = pack4(vb, T);
            ((uint2*)scond)[t] = cw;
        }
    }
    __syncthreads();

    // ---- Phase 2: vertical 7-sum, SIMD bytes, uint2 grid-stride (R8 verbatim)
    {
        const uint2* c2 = (const uint2*)scond;
        uint2* v2 = (uint2*)svsum;
        #pragma unroll 1
        for (int wi = tid; wi < TILE_H * W2PR; wi += NTHREADS) {
            uint2 s = c2[wi];
            #pragma unroll
            for (int k = 1; k < 7; k++) {
                uint2 a = c2[wi + k * W2PR];
                s.x += a.x; s.y += a.y;
            }
            v2[wi] = s;
        }
    }
    __syncthreads();

    // ---- Phase 3: same loads/stores as R8; SIMD prefix-sum horizontal + byte
    //      band mask + prmt sign-replicate select.
    const int tx = tid & 31;        // word group -> cols [4tx .. 4tx+3]
    const int ty = tid >> 5;
    const unsigned int* vrow = &svsum[ty * WPR + tx];
    const float* gp = xp + (long long)(r0 + ty) * W + c0 + (tx << 2);
    float* gop = op + (long long)(r0 + ty) * W + c0 + (tx << 2);

    #pragma unroll
    for (int rr = 0; rr < TILE_H; rr += 8) {
        unsigned w0 = vrow[0];
        unsigned w1 = vrow[1];
        unsigned w2 = vrow[2];

        // byte prefix sums over span a0..a11 (w0,w1,w2); P <= 84 < 128
        unsigned p0 = w0 * 0x01010101u;                       // P0..P3
        unsigned p1 = w1 * 0x01010101u + prmt(p0, 0, 0x3333); // P4..P7
        unsigned p2 = w2 * 0x01010101u + prmt(p1, 0, 0x3333); // P8..P11
        // h_i = P[i+7] - P[i], i = 0..3  (window bytes a_{i+1}..a_{i+7})
        unsigned hA = __vsub4(prmt(p1, p2, 0x6543), p0);

        // band 5..19 per byte -> MSB flag (h <= 49, carry-free)
        unsigned mA = (hA + 0x7B7B7B7Bu) & ~(hA + 0x6C6C6C6Cu) & 0x80808080u;

        float4 xv = *(const float4*)gp;
        float4 ov;
        ov.x = __uint_as_float(__float_as_uint(xv.x) & ~prmt(mA, 0, 0x8888));
        ov.y = __uint_as_float(__float_as_uint(xv.y) & ~prmt(mA, 0, 0x9999));
        ov.z = __uint_as_float(__float_as_uint(xv.z) & ~prmt(mA, 0, 0xAAAA));
        ov.w = __uint_as_float(__float_as_uint(xv.w) & ~prmt(mA, 0, 0xBBBB));

        __stcs((float4*)gop, ov);

        vrow += 8 * WPR;
        gp  += 8 * W;
        gop += 8 * W;
    }
}

extern "C" void kernel_launch(void* const* d_in, const int* in_sizes, int n_in,
                              void* d_out, int out_size) {
    const float* x = (const float*)d_in[0];
    float* out = (float*)d_out;
    const int H = 1024, W = 1024;
    const int planes = out_size / (H * W);   // B*C = 48
    dim3 grid(W / TILE_W, H / TILE_H, planes);
    backedge_kernel<<<grid, NTHREADS>>>(x, out, H, W);
}

// round 12
// speedup vs baseline: 1.2704x; 1.0276x over previous
#include <cuda_runtime.h>

// BackEdgeConv2d fused: out = x * !(5 <= boxcount7x7(x >= 128/255, reflect) <= 19)
// x: [16,3,1024,1024] fp32. R11 + __launch_bounds__(256,7) occupancy recovery:
//  - phase 1: interior fast path, sign-bit pack, word-PAIR tasks (17 uint2/row)
//  - phase 2: 7-load vertical sums, uint2 grid-stride
//  - phase 3: SIMD prefix-sum + byte band mask + prmt sign-replicate select

#define TILE_W 128
#define TILE_H 64
#define KPAD 3
#define PH (TILE_H + 2*KPAD)        // 70 padded rows
#define WPR 34                      // 136 cond bytes/row: byte j <-> global col c0-4+j
#define PPR 17                      // uint2 pairs per row (exactly 34 words)
#define W2PR 17                     // uint2 per row (phase 2 view)
#define NTHREADS 256

// PTX prmt: guaranteed default-mode semantics incl. selector-bit-3 MSB-replicate.
__device__ __forceinline__ unsigned prmt(unsigned a, unsigned b, unsigned s) {
    unsigned r;
    asm("prmt.b32 %0, %1, %2, %3;" : "=r"(r) : "r"(a), "r"(b), "r"(s));
    return r;
}

__device__ __forceinline__ unsigned pack4(float4 v, float T) {
    // cond = (x >= T) = !signbit(x - T); x==T -> +0 -> 1. Exact.
    unsigned a0 = __float_as_uint(v.x - T);
    unsigned a1 = __float_as_uint(v.y - T);
    unsigned a2 = __float_as_uint(v.z - T);
    unsigned a3 = __float_as_uint(v.w - T);
    unsigned sa = prmt(prmt(a0, a1, 0x0073), prmt(a2, a3, 0x0073), 0x5410);
    return ((~sa) & 0x80808080u) >> 7;          // 1/0 per byte
}

__global__ __launch_bounds__(NTHREADS, 7)
void backedge_kernel(const float* __restrict__ x, float* __restrict__ out,
                     int H, int W) {
    __shared__ __align__(16) unsigned int scond[PH * WPR];      // 9520 B
    __shared__ __align__(16) unsigned int svsum[TILE_H * WPR];  // 8704 B

    const int tid = threadIdx.x;
    const int c0 = blockIdx.x * TILE_W;
    const int r0 = blockIdx.y * TILE_H;
    const long long plane = (long long)blockIdx.z * H * W;
    const float* xp = x + plane;
    float* op = out + plane;
    const float T = 128.0f / 255.0f;

    // ---- Phase 1: padded binary cond map; one word-PAIR (8 px) per task.
    const bool interior = (c0 >= 4) && (c0 + TILE_W + 4 <= W) &&
                          (r0 >= KPAD) && (r0 + TILE_H + KPAD <= H);
    if (interior) {
        const float* base = xp + (r0 - KPAD) * W + (c0 - 4);
        #pragma unroll 1
        for (int t = tid; t < PH * PPR; t += NTHREADS) {
            int pr = t / PPR;                 // const divisor -> mul.hi
            int pw = t - pr * PPR;
            const float4* p = (const float4*)(base + pr * W + (pw << 3));
            float4 va = p[0], vb = p[1];
            uint2 cw;
            cw.x = pack4(va, T);
            cw.y = pack4(vb, T);
            ((uint2*)scond)[t] = cw;
        }
    } else {
        #pragma unroll 1
        for (int t = tid; t < PH * PPR; t += NTHREADS) {
            int pr = t / PPR;
            int pw = t - pr * PPR;
            int gr = r0 + pr - KPAD;
            int gc = c0 + (pw << 3) - 4;
            float4 va, vb;
            if ((unsigned)gr < (unsigned)H && (unsigned)gc <= (unsigned)(W - 8)) {
                const float4* p = (const float4*)(xp + gr * W + gc);
                va = p[0]; vb = p[1];
            } else {
                int rr = gr < 0 ? -gr : (gr >= H ? 2 * H - 2 - gr : gr);
                const float* rowp = xp + rr * W;
                float f[8];
                #pragma unroll
                for (int k = 0; k < 8; k++) {
                    int g = gc + k;
                    g = g < 0 ? -g : (g >= W ? 2 * W - 2 - g : g);
                    f[k] = rowp[g];
                }
                va = make_float4(f[0], f[1], f[2], f[3]);
                vb = make_float4(f[4], f[5], f[6], f[7]);
            }
            uint2 cw;
            cw.x = pack4(va, T);
            cw.y = pack4(vb, T);
            ((uint2*)scond)[t] = cw;
        }
    }
    __syncthreads();

    // ---- Phase 2: vertical 7-sum, SIMD bytes, uint2 grid-stride
    {
        const uint2* c2 = (const uint2*)scond;
        uint2* v2 = (uint2*)svsum;
        #pragma unroll 1
        for (int wi = tid; wi < TILE_H * W2PR; wi += NTHREADS) {
            uint2 s = c2[wi];
            #pragma unroll
            for (int k = 1; k < 7; k++) {
                uint2 a = c2[wi + k * W2PR];
                s.x += a.x; s.y += a.y;
            }
            v2[wi] = s;
        }
    }
    __syncthreads();

    // ---- Phase 3: SIMD prefix-sum horizontal + byte band mask + prmt select
    const int tx = tid & 31;        // word group -> cols [4tx .. 4tx+3]
    const int ty = tid >> 5;
    const unsigned int* vrow = &svsum[ty * WPR + tx];
    const float* gp = xp + (long long)(r0 + ty) * W + c0 + (tx << 2);
    float* gop = op + (long long)(r0 + ty) * W + c0 + (tx << 2);

    #pragma unroll
    for (int rr = 0; rr < TILE_H; rr += 8) {
        unsigned w0 = vrow[0];
        unsigned w1 = vrow[1];
        unsigned w2 = vrow[2];

        // byte prefix sums over span a0..a11 (w0,w1,w2); P <= 84 < 128
        unsigned p0 = w0 * 0x01010101u;                       // P0..P3
        unsigned p1 = w1 * 0x01010101u + prmt(p0, 0, 0x3333); // P4..P7
        unsigned p2 = w2 * 0x01010101u + prmt(p1, 0, 0x3333); // P8..P11
        // h_i = P[i+7] - P[i], i = 0..3  (window bytes a_{i+1}..a_{i+7})
        unsigned hA = __vsub4(prmt(p1, p2, 0x6543), p0);

        // band 5..19 per byte -> MSB flag (h <= 49, carry-free)
        unsigned mA = (hA + 0x7B7B7B7Bu) & ~(hA + 0x6C6C6C6Cu) & 0x80808080u;

        float4 xv = *(const float4*)gp;
        float4 ov;
        ov.x = __uint_as_float(__float_as_uint(xv.x) & ~prmt(mA, 0, 0x8888));
        ov.y = __uint_as_float(__float_as_uint(xv.y) & ~prmt(mA, 0, 0x9999));
        ov.z = __uint_as_float(__float_as_uint(xv.z) & ~prmt(mA, 0, 0xAAAA));
        ov.w = __uint_as_float(__float_as_uint(xv.w) & ~prmt(mA, 0, 0xBBBB));

        __stcs((float4*)gop, ov);

        vrow += 8 * WPR;
        gp  += 8 * W;
        gop += 8 * W;
    }
}

extern "C" void kernel_launch(void* const* d_in, const int* in_sizes, int n_in,
                              void* d_out, int out_size) {
    const float* x = (const float*)d_in[0];
    float* out = (float*)d_out;
    const int H = 1024, W = 1024;
    const int planes = out_size / (H * W);   // B*C = 48
    dim3 grid(W / TILE_W, H / TILE_H, planes);
    backedge_kernel<<<grid, NTHREADS>>>(x, out, H, W);
}